// round 2
// baseline (speedup 1.0000x reference)
#include <cuda_runtime.h>

#define BATCH 512
#define NV 6890
#define N3 20670      // NV*3
#define NP 20736      // padded N: 162*128
#define KDIM 224      // 207 (pose) + 10 (shape) + 7 zero pad
#define NJ 24
#define J54 54
#define NSEG 8
#define SEGLEN 864    // 27*32 ; 8*864 = 6912 >= 6890

// parent chain is a fixed constant of the problem definition
__constant__ int c_parent[23] = {0, 0, 0, 1, 2, 3, 4, 5, 6, 7, 8, 9,
                                 9, 9, 12, 13, 14, 16, 17, 18, 19, 20, 21};

// ---- scratch (static device globals; no allocation at runtime) ----
__device__ float g_JM[NJ * 3 * 11];            // J_regressor @ [shapedirs | v_template]
__device__ float g_Acat[BATCH * KDIM];         // [lrotmin | beta | 0] per batch
__device__ float g_Gc[BATCH * NJ * 12];        // corrected global transforms (3x4)
__device__ float g_Wt[KDIM * NP];              // transposed packed [posedirs|shapedirs]
__device__ float g_vposed[BATCH * N3];
__device__ float g_part[NSEG * BATCH * J54 * 3];
__device__ float g_pel[BATCH * 3];
__device__ int g_jmap64;                       // 1 if joint_map stored as int64

// ============================================================================
// K-1: sniff joint_map dtype (int32 vs int64). Values < 54, so if int64 the
// high 32-bit words (odd int32 offsets) are all zero. 24 samples => robust.
// Both read patterns stay within min(49*4, 49*8) bytes.
// ============================================================================
__global__ void sniff_kernel(const int* __restrict__ jmap) {
    if (threadIdx.x == 0) {
        int is64 = 1;
        for (int i = 0; i < 24; i++)
            if (jmap[2 * i + 1] != 0) is64 = 0;
        g_jmap64 = is64;
    }
}

// ============================================================================
// K0: JM[j][d][k] = sum_v Jreg[j,v] * (k<10 ? shapedirs[v,d,k] : v_template[v,d])
// ============================================================================
__global__ void jm_kernel(const float* __restrict__ Jreg,
                          const float* __restrict__ shapedirs,
                          const float* __restrict__ vtemp) {
    int j = blockIdx.x / 3, d = blockIdx.x % 3;
    int t = threadIdx.x;
    float acc[11];
#pragma unroll
    for (int k = 0; k < 11; k++) acc[k] = 0.f;
    const float* reg = Jreg + j * NV;
    for (int v = t; v < NV; v += 256) {
        float r = reg[v];
        const float* sd = shapedirs + (v * 3 + d) * 10;
#pragma unroll
        for (int k = 0; k < 10; k++) acc[k] += r * sd[k];
        acc[10] += r * vtemp[v * 3 + d];
    }
    __shared__ float red[256];
    for (int k = 0; k < 11; k++) {
        red[t] = acc[k];
        __syncthreads();
        for (int s = 128; s > 0; s >>= 1) {
            if (t < s) red[t] += red[t + s];
            __syncthreads();
        }
        if (t == 0) g_JM[(j * 3 + d) * 11 + k] = red[0];
        __syncthreads();
    }
}

// ============================================================================
// K1: per-batch rodrigues, lrotmin, J, kinematic chain, corrected transforms
// ============================================================================
__global__ void pose_kernel(const float* __restrict__ pose,
                            const float* __restrict__ beta) {
    int b = blockIdx.x, t = threadIdx.x;
    __shared__ float sR[NJ][9];
    __shared__ float sJ[NJ][3];
    __shared__ float sA[NJ][12];

    if (t < NJ) {
        float rx = pose[b * 72 + 3 * t + 0];
        float ry = pose[b * 72 + 3 * t + 1];
        float rz = pose[b * 72 + 3 * t + 2];
        float th = sqrtf(rx * rx + ry * ry + rz * rz);
        float inv = 1.f / fmaxf(th, 1e-8f);
        float kx = rx * inv, ky = ry * inv, kz = rz * inv;
        float s = sinf(th), c = cosf(th), C = 1.f - c;
        float kn2 = kx * kx + ky * ky + kz * kz;
        float R0 = 1.f + C * (kx * kx - kn2);
        float R1 = -s * kz + C * kx * ky;
        float R2 = s * ky + C * kx * kz;
        float R3 = s * kz + C * ky * kx;
        float R4 = 1.f + C * (ky * ky - kn2);
        float R5 = -s * kx + C * ky * kz;
        float R6 = -s * ky + C * kz * kx;
        float R7 = s * kx + C * kz * ky;
        float R8 = 1.f + C * (kz * kz - kn2);
        sR[t][0] = R0; sR[t][1] = R1; sR[t][2] = R2;
        sR[t][3] = R3; sR[t][4] = R4; sR[t][5] = R5;
        sR[t][6] = R6; sR[t][7] = R7; sR[t][8] = R8;
        if (t >= 1) {
            float* dst = g_Acat + b * KDIM + (t - 1) * 9;
            dst[0] = R0 - 1.f; dst[1] = R1;       dst[2] = R2;
            dst[3] = R3;       dst[4] = R4 - 1.f; dst[5] = R5;
            dst[6] = R6;       dst[7] = R7;       dst[8] = R8 - 1.f;
        }
#pragma unroll
        for (int d = 0; d < 3; d++) {
            const float* m = g_JM + (t * 3 + d) * 11;
            float val = m[10];
#pragma unroll
            for (int k = 0; k < 10; k++) val += m[k] * beta[b * 10 + k];
            sJ[t][d] = val;
        }
    }
    if (t == 0) {
#pragma unroll
        for (int k = 0; k < 10; k++) g_Acat[b * KDIM + 207 + k] = beta[b * 10 + k];
#pragma unroll
        for (int k = 217; k < KDIM; k++) g_Acat[b * KDIM + k] = 0.f;
    }
    __syncwarp();
    if (t == 0) {
        // root
#pragma unroll
        for (int e = 0; e < 9; e++) sA[0][(e / 3) * 4 + (e % 3)] = sR[0][e];
        sA[0][3] = sJ[0][0]; sA[0][7] = sJ[0][1]; sA[0][11] = sJ[0][2];
        for (int i = 1; i < NJ; i++) {
            int p = c_parent[i - 1];
            float lt0 = sJ[i][0] - sJ[p][0];
            float lt1 = sJ[i][1] - sJ[p][1];
            float lt2 = sJ[i][2] - sJ[p][2];
            for (int r = 0; r < 3; r++) {
                float p0 = sA[p][r * 4 + 0], p1 = sA[p][r * 4 + 1];
                float p2 = sA[p][r * 4 + 2], p3 = sA[p][r * 4 + 3];
                for (int cc = 0; cc < 3; cc++)
                    sA[i][r * 4 + cc] = p0 * sR[i][0 * 3 + cc] + p1 * sR[i][1 * 3 + cc] + p2 * sR[i][2 * 3 + cc];
                sA[i][r * 4 + 3] = p0 * lt0 + p1 * lt1 + p2 * lt2 + p3;
            }
        }
    }
    __syncwarp();
    if (t < NJ) {
        float j0 = sJ[t][0], j1 = sJ[t][1], j2 = sJ[t][2];
        float* dst = g_Gc + (b * NJ + t) * 12;
#pragma unroll
        for (int r = 0; r < 3; r++) {
            float a0 = sA[t][r * 4 + 0], a1 = sA[t][r * 4 + 1];
            float a2 = sA[t][r * 4 + 2], a3 = sA[t][r * 4 + 3];
            dst[r * 4 + 0] = a0; dst[r * 4 + 1] = a1; dst[r * 4 + 2] = a2;
            dst[r * 4 + 3] = a3 - (a0 * j0 + a1 * j1 + a2 * j2);
        }
    }
}

// ============================================================================
// K2: pack W^T[k][n]  (k<207: posedirs, 207..216: shapedirs, rest 0)
// ============================================================================
__global__ void pack_kernel(const float* __restrict__ posedirs,
                            const float* __restrict__ shapedirs) {
    __shared__ float s[32 * 225];
    int n0 = blockIdx.x * 32;
    int t = threadIdx.x;
    for (int idx = t; idx < 32 * 207; idx += 256) {
        int n = idx / 207, k = idx % 207;
        int gn = n0 + n;
        s[n * 225 + k] = (gn < N3) ? posedirs[gn * 207 + k] : 0.f;
    }
    for (int idx = t; idx < 32 * 10; idx += 256) {
        int n = idx / 10, k = idx % 10;
        int gn = n0 + n;
        s[n * 225 + 207 + k] = (gn < N3) ? shapedirs[gn * 10 + k] : 0.f;
    }
    for (int idx = t; idx < 32 * 7; idx += 256) {
        int n = idx / 7, k = idx % 7;
        s[n * 225 + 217 + k] = 0.f;
    }
    __syncthreads();
    for (int idx = t; idx < KDIM * 32; idx += 256) {
        int k = idx / 32, n = idx % 32;
        g_Wt[k * NP + n0 + n] = s[n * 225 + k];
    }
}

// ============================================================================
// K3: SGEMM  v_posed[m][n] = v_template[n] + sum_k Acat[m][k] * Wt[k][n]
//     128x128x8 tiles, 8x8 per thread
// ============================================================================
__global__ void __launch_bounds__(256) gemm_kernel(const float* __restrict__ vtemp) {
    __shared__ __align__(16) float As[8][132];
    __shared__ __align__(16) float Bs[8][128];
    int tid = threadIdx.x;
    int ty = tid / 16, tx = tid % 16;
    int m0 = blockIdx.y * 128;
    int n0 = blockIdx.x * 128;
    float acc[8][8];
#pragma unroll
    for (int i = 0; i < 8; i++)
#pragma unroll
        for (int j = 0; j < 8; j++) acc[i][j] = 0.f;

    const int arow = tid >> 1, ahalf = tid & 1;
    const int bkr = tid >> 5, bnc = (tid & 31) << 2;

    for (int k0 = 0; k0 < KDIM; k0 += 8) {
        float4 av = *(const float4*)(g_Acat + (m0 + arow) * KDIM + k0 + ahalf * 4);
        float4 bv = *(const float4*)(g_Wt + (size_t)(k0 + bkr) * NP + n0 + bnc);
        __syncthreads();
        As[ahalf * 4 + 0][arow] = av.x;
        As[ahalf * 4 + 1][arow] = av.y;
        As[ahalf * 4 + 2][arow] = av.z;
        As[ahalf * 4 + 3][arow] = av.w;
        *(float4*)&Bs[bkr][bnc] = bv;
        __syncthreads();
#pragma unroll
        for (int kk = 0; kk < 8; kk++) {
            float ar[8], br[8];
            *(float4*)&ar[0] = *(const float4*)&As[kk][ty * 8];
            *(float4*)&ar[4] = *(const float4*)&As[kk][ty * 8 + 4];
            *(float4*)&br[0] = *(const float4*)&Bs[kk][tx * 8];
            *(float4*)&br[4] = *(const float4*)&Bs[kk][tx * 8 + 4];
#pragma unroll
            for (int i = 0; i < 8; i++)
#pragma unroll
                for (int j = 0; j < 8; j++) acc[i][j] += ar[i] * br[j];
        }
    }
#pragma unroll
    for (int i = 0; i < 8; i++) {
        int gm = m0 + ty * 8 + i;
#pragma unroll
        for (int j = 0; j < 8; j++) {
            int gn = n0 + tx * 8 + j;
            if (gn < N3) g_vposed[gm * N3 + gn] = acc[i][j] + vtemp[gn];
        }
    }
}

// ============================================================================
// K4: LBS skinning. 128 verts x 8 batches per block. Writes unshifted v to out.
// ============================================================================
__global__ void __launch_bounds__(128) skin_kernel(const float* __restrict__ weights,
                                                   float* __restrict__ out) {
    __shared__ __align__(16) float sGc[8 * NJ * 12];
    int b0 = blockIdx.y * 8;
    int v = blockIdx.x * 128 + threadIdx.x;
    for (int idx = threadIdx.x; idx < 8 * NJ * 12; idx += 128)
        sGc[idx] = g_Gc[b0 * NJ * 12 + idx];
    __syncthreads();
    if (v >= NV) return;
    float w[NJ];
#pragma unroll
    for (int j = 0; j < NJ; j++) w[j] = weights[v * NJ + j];
#pragma unroll 1
    for (int bb = 0; bb < 8; bb++) {
        float T[12];
#pragma unroll
        for (int c = 0; c < 12; c++) T[c] = 0.f;
        const float4* gc = (const float4*)(sGc + bb * NJ * 12);
#pragma unroll
        for (int j = 0; j < NJ; j++) {
            float wj = w[j];
            float4 r0 = gc[j * 3 + 0];
            float4 r1 = gc[j * 3 + 1];
            float4 r2 = gc[j * 3 + 2];
            T[0] += wj * r0.x; T[1] += wj * r0.y; T[2] += wj * r0.z; T[3] += wj * r0.w;
            T[4] += wj * r1.x; T[5] += wj * r1.y; T[6] += wj * r1.z; T[7] += wj * r1.w;
            T[8] += wj * r2.x; T[9] += wj * r2.y; T[10] += wj * r2.z; T[11] += wj * r2.w;
        }
        const float* vp = g_vposed + (b0 + bb) * N3 + v * 3;
        float p0 = vp[0], p1 = vp[1], p2 = vp[2];
        float* o = out + (b0 + bb) * N3 + v * 3;
        o[0] = T[0] * p0 + T[1] * p1 + T[2] * p2 + T[3];
        o[1] = T[4] * p0 + T[5] * p1 + T[6] * p2 + T[7];
        o[2] = T[8] * p0 + T[9] * p1 + T[10] * p2 + T[11];
    }
}

// ============================================================================
// K5: joint regression partials. Block = (16 batches) x (all 54 joints),
//     K-split into NSEG segments. 64x48 tile, 4x3 per thread.
// ============================================================================
__global__ void __launch_bounds__(256) joints_kernel(const float* __restrict__ Jreg,
                                                     const float* __restrict__ Jspin,
                                                     const float* __restrict__ Jextra,
                                                     const float* __restrict__ outv) {
    __shared__ __align__(16) float sreg[32 * 68];
    __shared__ float sv[32 * 48];
    int gb = blockIdx.x;    // 0..31
    int seg = blockIdx.y;   // 0..7
    int b0 = gb * 16;
    int tid = threadIdx.x;
    int ty = tid / 16, tx = tid % 16;
    int j0 = ty * 4;
    float acc[4][3];
#pragma unroll
    for (int i = 0; i < 4; i++)
#pragma unroll
        for (int d = 0; d < 3; d++) acc[i][d] = 0.f;

    int kbeg = seg * SEGLEN;
    for (int k0 = kbeg; k0 < kbeg + SEGLEN; k0 += 32) {
        for (int idx = tid; idx < 64 * 32; idx += 256) {
            int j = idx >> 5, vv = idx & 31;
            int gk = k0 + vv;
            float val = 0.f;
            if (j < J54 && gk < NV) {
                const float* row = (j < 24) ? (Jreg + j * NV)
                                 : (j < 45) ? (Jspin + (j - 24) * NV)
                                            : (Jextra + (j - 45) * NV);
                val = row[gk];
            }
            sreg[vv * 68 + j] = val;
        }
        for (int idx = tid; idx < 16 * 96; idx += 256) {
            int bb = idx / 96, rem = idx % 96;
            int gk = k0 + rem / 3;
            float val = (gk < NV) ? outv[(b0 + bb) * N3 + k0 * 3 + rem] : 0.f;
            sv[(rem / 3) * 48 + bb * 3 + rem % 3] = val;
        }
        __syncthreads();
#pragma unroll
        for (int vv = 0; vv < 32; vv++) {
            float4 a = *(const float4*)&sreg[vv * 68 + j0];
            float bx = sv[vv * 48 + tx * 3 + 0];
            float by = sv[vv * 48 + tx * 3 + 1];
            float bz = sv[vv * 48 + tx * 3 + 2];
            acc[0][0] += a.x * bx; acc[0][1] += a.x * by; acc[0][2] += a.x * bz;
            acc[1][0] += a.y * bx; acc[1][1] += a.y * by; acc[1][2] += a.y * bz;
            acc[2][0] += a.z * bx; acc[2][1] += a.z * by; acc[2][2] += a.z * bz;
            acc[3][0] += a.w * bx; acc[3][1] += a.w * by; acc[3][2] += a.w * bz;
        }
        __syncthreads();
    }
    int b = b0 + tx;
#pragma unroll
    for (int i = 0; i < 4; i++) {
        int j = j0 + i;
        if (j < J54) {
#pragma unroll
            for (int d = 0; d < 3; d++)
                g_part[((seg * BATCH + b) * J54 + j) * 3 + d] = acc[i][d];
        }
    }
}

// ============================================================================
// K6: sum partials, gather by joint_map, pelvis, write joints & pelvis outputs
// joint_map dtype (int32 vs int64) chosen via g_jmap64 sniffed flag.
// ============================================================================
__global__ void finalize_kernel(const int* __restrict__ jmap,
                                float* __restrict__ out) {
    int b = blockIdx.x, t = threadIdx.x;  // 192 threads
    __shared__ float jall[J54 * 3];
    __shared__ float pel[3];
    int is64 = g_jmap64;
    if (t < 162) {
        float s = 0.f;
        for (int seg = 0; seg < NSEG; seg++)
            s += g_part[(seg * BATCH + b) * (J54 * 3) + t];
        jall[t] = s;
    }
    __syncthreads();
    if (t < 3) {
        int a = is64 ? jmap[2 * 27] : jmap[27];
        int c = is64 ? jmap[2 * 28] : jmap[28];
        float p = 0.5f * (jall[a * 3 + t] + jall[c * 3 + t]);
        pel[t] = p;
        g_pel[b * 3 + t] = p;
        out[(size_t)BATCH * N3 + (size_t)BATCH * 147 + b * 3 + t] = p;
    }
    __syncthreads();
    if (t < 147) {
        int i = t / 3, d = t % 3;
        int j = is64 ? jmap[2 * i] : jmap[i];
        out[(size_t)BATCH * N3 + b * 147 + t] = jall[j * 3 + d] - pel[d];
    }
}

// ============================================================================
// K7: v -= pelvis (in place on d_out vertex region)
// ============================================================================
__global__ void subv_kernel(float* __restrict__ out) {
    int idx = blockIdx.x * 256 + threadIdx.x;
    if (idx < BATCH * N3) {
        int b = idx / N3;
        int d = idx % 3;  // N3 and per-batch base are multiples of 3
        out[idx] -= g_pel[b * 3 + d];
    }
}

// ============================================================================
extern "C" void kernel_launch(void* const* d_in, const int* in_sizes, int n_in,
                              void* d_out, int out_size) {
    const float* pose      = (const float*)d_in[0];
    const float* beta      = (const float*)d_in[1];
    const float* vtemp     = (const float*)d_in[2];
    const float* shapedirs = (const float*)d_in[3];
    const float* posedirs  = (const float*)d_in[4];
    const float* weights   = (const float*)d_in[5];
    const float* Jreg      = (const float*)d_in[6];
    const float* Jspin     = (const float*)d_in[7];
    const float* Jextra    = (const float*)d_in[8];
    const int* jmap        = (const int*)d_in[10];
    float* out = (float*)d_out;

    sniff_kernel<<<1, 32>>>(jmap);
    jm_kernel<<<72, 256>>>(Jreg, shapedirs, vtemp);
    pose_kernel<<<BATCH, 32>>>(pose, beta);
    pack_kernel<<<NP / 32, 256>>>(posedirs, shapedirs);
    gemm_kernel<<<dim3(NP / 128, BATCH / 128), 256>>>(vtemp);
    skin_kernel<<<dim3((NV + 127) / 128, BATCH / 8), 128>>>(weights, out);
    joints_kernel<<<dim3(BATCH / 16, NSEG), 256>>>(Jreg, Jspin, Jextra, out);
    finalize_kernel<<<BATCH, 192>>>(jmap, out);
    subv_kernel<<<(BATCH * N3 + 255) / 256, 256>>>(out);
}

// round 3
// speedup vs baseline: 1.2759x; 1.2759x over previous
#include <cuda_runtime.h>
#include <cstdint>

#define BATCH 512
#define NV 6890
#define N3 20670      // NV*3
#define NP 20736      // padded N: 162*128
#define KDIM 224      // 207 (pose) + 10 (shape) + 7 zero pad
#define NJ 24
#define J54 54
#define NSEG 8
#define SEGLEN 864    // 27*32 ; 8*864 = 6912 >= 6890
#define KC 16         // GEMM k-chunk

// parent chain is a fixed constant of the problem definition
__constant__ int c_parent[23] = {0, 0, 0, 1, 2, 3, 4, 5, 6, 7, 8, 9,
                                 9, 9, 12, 13, 14, 16, 17, 18, 19, 20, 21};

// ---- scratch (static device globals; no allocation at runtime) ----
__device__ float g_JM[NJ * 3 * 11];
__device__ float g_Acat[BATCH * KDIM];         // [lrotmin | beta | 0] per batch
__device__ float g_At[KDIM * BATCH];           // transposed, tf32-rounded
__device__ float g_Gc[BATCH * NJ * 12];
__device__ float g_Wt[KDIM * NP];              // k-major packed weights, tf32-rounded
__device__ float g_vposed[BATCH * N3];
__device__ float g_part[NSEG * BATCH * J54 * 3];
__device__ float g_pel[BATCH * 3];
__device__ int g_jmap64;

__device__ __forceinline__ float to_tf32(float v) {
    uint32_t o;
    asm("cvt.rna.tf32.f32 %0, %1;" : "=r"(o) : "f"(v));
    return __uint_as_float(o);
}

__device__ __forceinline__ void mma_tf32(float* c, const uint32_t* a, const uint32_t* b) {
    asm volatile(
        "mma.sync.aligned.m16n8k8.row.col.f32.tf32.tf32.f32 "
        "{%0,%1,%2,%3}, {%4,%5,%6,%7}, {%8,%9}, {%0,%1,%2,%3};\n"
        : "+f"(c[0]), "+f"(c[1]), "+f"(c[2]), "+f"(c[3])
        : "r"(a[0]), "r"(a[1]), "r"(a[2]), "r"(a[3]), "r"(b[0]), "r"(b[1]));
}

// ============================================================================
// sniff joint_map dtype (int32 vs int64)
// ============================================================================
__global__ void sniff_kernel(const int* __restrict__ jmap) {
    if (threadIdx.x == 0) {
        int is64 = 1;
        for (int i = 0; i < 24; i++)
            if (jmap[2 * i + 1] != 0) is64 = 0;
        g_jmap64 = is64;
    }
}

// ============================================================================
// K0: JM[j][d][k] = sum_v Jreg[j,v] * (k<10 ? shapedirs[v,d,k] : v_template[v,d])
// ============================================================================
__global__ void jm_kernel(const float* __restrict__ Jreg,
                          const float* __restrict__ shapedirs,
                          const float* __restrict__ vtemp) {
    int j = blockIdx.x / 3, d = blockIdx.x % 3;
    int t = threadIdx.x;
    float acc[11];
#pragma unroll
    for (int k = 0; k < 11; k++) acc[k] = 0.f;
    const float* reg = Jreg + j * NV;
    for (int v = t; v < NV; v += 256) {
        float r = reg[v];
        const float* sd = shapedirs + (v * 3 + d) * 10;
#pragma unroll
        for (int k = 0; k < 10; k++) acc[k] += r * sd[k];
        acc[10] += r * vtemp[v * 3 + d];
    }
    __shared__ float red[256];
    for (int k = 0; k < 11; k++) {
        red[t] = acc[k];
        __syncthreads();
        for (int s = 128; s > 0; s >>= 1) {
            if (t < s) red[t] += red[t + s];
            __syncthreads();
        }
        if (t == 0) g_JM[(j * 3 + d) * 11 + k] = red[0];
        __syncthreads();
    }
}

// ============================================================================
// K1: rodrigues, lrotmin, J, kinematic chain, corrected transforms
// ============================================================================
__global__ void pose_kernel(const float* __restrict__ pose,
                            const float* __restrict__ beta) {
    int b = blockIdx.x, t = threadIdx.x;
    __shared__ float sR[NJ][9];
    __shared__ float sJ[NJ][3];
    __shared__ float sA[NJ][12];

    if (t < NJ) {
        float rx = pose[b * 72 + 3 * t + 0];
        float ry = pose[b * 72 + 3 * t + 1];
        float rz = pose[b * 72 + 3 * t + 2];
        float th = sqrtf(rx * rx + ry * ry + rz * rz);
        float inv = 1.f / fmaxf(th, 1e-8f);
        float kx = rx * inv, ky = ry * inv, kz = rz * inv;
        float s = sinf(th), c = cosf(th), C = 1.f - c;
        float kn2 = kx * kx + ky * ky + kz * kz;
        float R0 = 1.f + C * (kx * kx - kn2);
        float R1 = -s * kz + C * kx * ky;
        float R2 = s * ky + C * kx * kz;
        float R3 = s * kz + C * ky * kx;
        float R4 = 1.f + C * (ky * ky - kn2);
        float R5 = -s * kx + C * ky * kz;
        float R6 = -s * ky + C * kz * kx;
        float R7 = s * kx + C * kz * ky;
        float R8 = 1.f + C * (kz * kz - kn2);
        sR[t][0] = R0; sR[t][1] = R1; sR[t][2] = R2;
        sR[t][3] = R3; sR[t][4] = R4; sR[t][5] = R5;
        sR[t][6] = R6; sR[t][7] = R7; sR[t][8] = R8;
        if (t >= 1) {
            float* dst = g_Acat + b * KDIM + (t - 1) * 9;
            dst[0] = R0 - 1.f; dst[1] = R1;       dst[2] = R2;
            dst[3] = R3;       dst[4] = R4 - 1.f; dst[5] = R5;
            dst[6] = R6;       dst[7] = R7;       dst[8] = R8 - 1.f;
        }
#pragma unroll
        for (int d = 0; d < 3; d++) {
            const float* m = g_JM + (t * 3 + d) * 11;
            float val = m[10];
#pragma unroll
            for (int k = 0; k < 10; k++) val += m[k] * beta[b * 10 + k];
            sJ[t][d] = val;
        }
    }
    if (t == 0) {
#pragma unroll
        for (int k = 0; k < 10; k++) g_Acat[b * KDIM + 207 + k] = beta[b * 10 + k];
#pragma unroll
        for (int k = 217; k < KDIM; k++) g_Acat[b * KDIM + k] = 0.f;
    }
    __syncwarp();
    if (t == 0) {
#pragma unroll
        for (int e = 0; e < 9; e++) sA[0][(e / 3) * 4 + (e % 3)] = sR[0][e];
        sA[0][3] = sJ[0][0]; sA[0][7] = sJ[0][1]; sA[0][11] = sJ[0][2];
        for (int i = 1; i < NJ; i++) {
            int p = c_parent[i - 1];
            float lt0 = sJ[i][0] - sJ[p][0];
            float lt1 = sJ[i][1] - sJ[p][1];
            float lt2 = sJ[i][2] - sJ[p][2];
            for (int r = 0; r < 3; r++) {
                float p0 = sA[p][r * 4 + 0], p1 = sA[p][r * 4 + 1];
                float p2 = sA[p][r * 4 + 2], p3 = sA[p][r * 4 + 3];
                for (int cc = 0; cc < 3; cc++)
                    sA[i][r * 4 + cc] = p0 * sR[i][0 * 3 + cc] + p1 * sR[i][1 * 3 + cc] + p2 * sR[i][2 * 3 + cc];
                sA[i][r * 4 + 3] = p0 * lt0 + p1 * lt1 + p2 * lt2 + p3;
            }
        }
    }
    __syncwarp();
    if (t < NJ) {
        float j0 = sJ[t][0], j1 = sJ[t][1], j2 = sJ[t][2];
        float* dst = g_Gc + (b * NJ + t) * 12;
#pragma unroll
        for (int r = 0; r < 3; r++) {
            float a0 = sA[t][r * 4 + 0], a1 = sA[t][r * 4 + 1];
            float a2 = sA[t][r * 4 + 2], a3 = sA[t][r * 4 + 3];
            dst[r * 4 + 0] = a0; dst[r * 4 + 1] = a1; dst[r * 4 + 2] = a2;
            dst[r * 4 + 3] = a3 - (a0 * j0 + a1 * j1 + a2 * j2);
        }
    }
}

// ============================================================================
// K1b: transpose Acat -> At [KDIM][512], tf32-rounded
// ============================================================================
__global__ void at_kernel() {
    int idx = blockIdx.x * 256 + threadIdx.x;   // grid covers KDIM*BATCH exactly
    int k = idx / BATCH, m = idx % BATCH;
    g_At[k * BATCH + m] = to_tf32(g_Acat[m * KDIM + k]);
}

// ============================================================================
// K2: pack W^T[k][n] (tf32-rounded)
// ============================================================================
__global__ void pack_kernel(const float* __restrict__ posedirs,
                            const float* __restrict__ shapedirs) {
    __shared__ float s[32 * 225];
    int n0 = blockIdx.x * 32;
    int t = threadIdx.x;
    for (int idx = t; idx < 32 * 207; idx += 256) {
        int n = idx / 207, k = idx % 207;
        int gn = n0 + n;
        s[n * 225 + k] = (gn < N3) ? posedirs[gn * 207 + k] : 0.f;
    }
    for (int idx = t; idx < 32 * 10; idx += 256) {
        int n = idx / 10, k = idx % 10;
        int gn = n0 + n;
        s[n * 225 + 207 + k] = (gn < N3) ? shapedirs[gn * 10 + k] : 0.f;
    }
    for (int idx = t; idx < 32 * 7; idx += 256) {
        int n = idx / 7, k = idx % 7;
        s[n * 225 + 217 + k] = 0.f;
    }
    __syncthreads();
    for (int idx = t; idx < KDIM * 32; idx += 256) {
        int k = idx / 32, n = idx % 32;
        g_Wt[k * NP + n0 + n] = to_tf32(s[n * 225 + k]);
    }
}

// ============================================================================
// K3: TF32 tensor-core GEMM.  v_posed = At^T @ Wt + v_template
// Block 128x128, 8 warps (2x4), warp tile 64x32, cp.async double-buffered K=16
// ============================================================================
__global__ void __launch_bounds__(256, 2) gemm_tf32_kernel(const float* __restrict__ vtemp) {
    __shared__ __align__(16) float As[2][KC][132];
    __shared__ __align__(16) float Bs[2][KC][132];
    int tid = threadIdx.x;
    int lane = tid & 31, wid = tid >> 5;
    int warp_m = wid & 1, warp_n = wid >> 1;
    int gq = lane >> 2, tq = lane & 3;
    int m0 = blockIdx.y * 128;
    int n0 = blockIdx.x * 128;

    float acc[4][4][4];
#pragma unroll
    for (int mt = 0; mt < 4; mt++)
#pragma unroll
        for (int nt = 0; nt < 4; nt++)
#pragma unroll
            for (int i = 0; i < 4; i++) acc[mt][nt][i] = 0.f;

    const int NSTAGE = KDIM / KC;  // 14

#define LOAD_STAGE(s, buf)                                                          \
    {                                                                               \
        int k0 = (s) * KC;                                                          \
        _Pragma("unroll")                                                           \
        for (int i = 0; i < 2; i++) {                                               \
            int idx = tid + i * 256;                                                \
            int k = idx >> 5, mg = (idx & 31) << 2;                                 \
            unsigned da = (unsigned)__cvta_generic_to_shared(&As[buf][k][mg]);      \
            const float* sa = g_At + (k0 + k) * BATCH + m0 + mg;                    \
            asm volatile("cp.async.cg.shared.global [%0], [%1], 16;" ::"r"(da), "l"(sa)); \
            unsigned db = (unsigned)__cvta_generic_to_shared(&Bs[buf][k][mg]);      \
            const float* sb = g_Wt + (size_t)(k0 + k) * NP + n0 + mg;               \
            asm volatile("cp.async.cg.shared.global [%0], [%1], 16;" ::"r"(db), "l"(sb)); \
        }                                                                           \
        asm volatile("cp.async.commit_group;");                                     \
    }

    LOAD_STAGE(0, 0);
    for (int s = 0; s < NSTAGE; s++) {
        int buf = s & 1;
        if (s + 1 < NSTAGE) {
            LOAD_STAGE(s + 1, buf ^ 1);
            asm volatile("cp.async.wait_group 1;");
        } else {
            asm volatile("cp.async.wait_group 0;");
        }
        __syncthreads();
#pragma unroll
        for (int kk = 0; kk < KC / 8; kk++) {
            int kb = kk * 8;
            uint32_t af[4][4], bf[4][2];
#pragma unroll
            for (int mt = 0; mt < 4; mt++) {
                int r = warp_m * 64 + mt * 16 + gq;
                af[mt][0] = __float_as_uint(As[buf][kb + tq][r]);
                af[mt][1] = __float_as_uint(As[buf][kb + tq][r + 8]);
                af[mt][2] = __float_as_uint(As[buf][kb + tq + 4][r]);
                af[mt][3] = __float_as_uint(As[buf][kb + tq + 4][r + 8]);
            }
#pragma unroll
            for (int nt = 0; nt < 4; nt++) {
                int cn = warp_n * 32 + nt * 8 + gq;
                bf[nt][0] = __float_as_uint(Bs[buf][kb + tq][cn]);
                bf[nt][1] = __float_as_uint(Bs[buf][kb + tq + 4][cn]);
            }
#pragma unroll
            for (int mt = 0; mt < 4; mt++)
#pragma unroll
                for (int nt = 0; nt < 4; nt++)
                    mma_tf32(acc[mt][nt], af[mt], bf[nt]);
        }
        __syncthreads();
    }

    // epilogue: add v_template, write float2 pairs
#pragma unroll
    for (int mt = 0; mt < 4; mt++) {
        int row = m0 + warp_m * 64 + mt * 16 + gq;
#pragma unroll
        for (int nt = 0; nt < 4; nt++) {
            int cn = n0 + warp_n * 32 + nt * 8 + 2 * tq;
            if (cn < N3) {
                float2 vt = *(const float2*)(vtemp + cn);
                float2 o0 = {acc[mt][nt][0] + vt.x, acc[mt][nt][1] + vt.y};
                float2 o1 = {acc[mt][nt][2] + vt.x, acc[mt][nt][3] + vt.y};
                *(float2*)(g_vposed + row * N3 + cn) = o0;
                *(float2*)(g_vposed + (row + 8) * N3 + cn) = o1;
            }
        }
    }
#undef LOAD_STAGE
}

// ============================================================================
// K4: LBS skinning. 128 verts x 8 batches per block.
// ============================================================================
__global__ void __launch_bounds__(128) skin_kernel(const float* __restrict__ weights,
                                                   float* __restrict__ out) {
    __shared__ __align__(16) float sGc[8 * NJ * 12];
    int b0 = blockIdx.y * 8;
    int v = blockIdx.x * 128 + threadIdx.x;
    for (int idx = threadIdx.x; idx < 8 * NJ * 12; idx += 128)
        sGc[idx] = g_Gc[b0 * NJ * 12 + idx];
    __syncthreads();
    if (v >= NV) return;
    float w[NJ];
#pragma unroll
    for (int j = 0; j < NJ; j++) w[j] = weights[v * NJ + j];
#pragma unroll 1
    for (int bb = 0; bb < 8; bb++) {
        float T[12];
#pragma unroll
        for (int c = 0; c < 12; c++) T[c] = 0.f;
        const float4* gc = (const float4*)(sGc + bb * NJ * 12);
#pragma unroll
        for (int j = 0; j < NJ; j++) {
            float wj = w[j];
            float4 r0 = gc[j * 3 + 0];
            float4 r1 = gc[j * 3 + 1];
            float4 r2 = gc[j * 3 + 2];
            T[0] += wj * r0.x; T[1] += wj * r0.y; T[2] += wj * r0.z; T[3] += wj * r0.w;
            T[4] += wj * r1.x; T[5] += wj * r1.y; T[6] += wj * r1.z; T[7] += wj * r1.w;
            T[8] += wj * r2.x; T[9] += wj * r2.y; T[10] += wj * r2.z; T[11] += wj * r2.w;
        }
        const float* vp = g_vposed + (b0 + bb) * N3 + v * 3;
        float p0 = vp[0], p1 = vp[1], p2 = vp[2];
        float* o = out + (b0 + bb) * N3 + v * 3;
        o[0] = T[0] * p0 + T[1] * p1 + T[2] * p2 + T[3];
        o[1] = T[4] * p0 + T[5] * p1 + T[6] * p2 + T[7];
        o[2] = T[8] * p0 + T[9] * p1 + T[10] * p2 + T[11];
    }
}

// ============================================================================
// K5: joint regression partials
// ============================================================================
__global__ void __launch_bounds__(256) joints_kernel(const float* __restrict__ Jreg,
                                                     const float* __restrict__ Jspin,
                                                     const float* __restrict__ Jextra,
                                                     const float* __restrict__ outv) {
    __shared__ __align__(16) float sreg[32 * 68];
    __shared__ float sv[32 * 48];
    int gb = blockIdx.x;
    int seg = blockIdx.y;
    int b0 = gb * 16;
    int tid = threadIdx.x;
    int ty = tid / 16, tx = tid % 16;
    int j0 = ty * 4;
    float acc[4][3];
#pragma unroll
    for (int i = 0; i < 4; i++)
#pragma unroll
        for (int d = 0; d < 3; d++) acc[i][d] = 0.f;

    int kbeg = seg * SEGLEN;
    for (int k0 = kbeg; k0 < kbeg + SEGLEN; k0 += 32) {
        for (int idx = tid; idx < 64 * 32; idx += 256) {
            int j = idx >> 5, vv = idx & 31;
            int gk = k0 + vv;
            float val = 0.f;
            if (j < J54 && gk < NV) {
                const float* row = (j < 24) ? (Jreg + j * NV)
                                 : (j < 45) ? (Jspin + (j - 24) * NV)
                                            : (Jextra + (j - 45) * NV);
                val = row[gk];
            }
            sreg[vv * 68 + j] = val;
        }
        for (int idx = tid; idx < 16 * 96; idx += 256) {
            int bb = idx / 96, rem = idx % 96;
            int gk = k0 + rem / 3;
            float val = (gk < NV) ? outv[(b0 + bb) * N3 + k0 * 3 + rem] : 0.f;
            sv[(rem / 3) * 48 + bb * 3 + rem % 3] = val;
        }
        __syncthreads();
#pragma unroll
        for (int vv = 0; vv < 32; vv++) {
            float4 a = *(const float4*)&sreg[vv * 68 + j0];
            float bx = sv[vv * 48 + tx * 3 + 0];
            float by = sv[vv * 48 + tx * 3 + 1];
            float bz = sv[vv * 48 + tx * 3 + 2];
            acc[0][0] += a.x * bx; acc[0][1] += a.x * by; acc[0][2] += a.x * bz;
            acc[1][0] += a.y * bx; acc[1][1] += a.y * by; acc[1][2] += a.y * bz;
            acc[2][0] += a.z * bx; acc[2][1] += a.z * by; acc[2][2] += a.z * bz;
            acc[3][0] += a.w * bx; acc[3][1] += a.w * by; acc[3][2] += a.w * bz;
        }
        __syncthreads();
    }
    int b = b0 + tx;
#pragma unroll
    for (int i = 0; i < 4; i++) {
        int j = j0 + i;
        if (j < J54) {
#pragma unroll
            for (int d = 0; d < 3; d++)
                g_part[((seg * BATCH + b) * J54 + j) * 3 + d] = acc[i][d];
        }
    }
}

// ============================================================================
// K6: sum partials, gather, pelvis, write joints & pelvis outputs
// ============================================================================
__global__ void finalize_kernel(const int* __restrict__ jmap,
                                float* __restrict__ out) {
    int b = blockIdx.x, t = threadIdx.x;
    __shared__ float jall[J54 * 3];
    __shared__ float pel[3];
    int is64 = g_jmap64;
    if (t < 162) {
        float s = 0.f;
        for (int seg = 0; seg < NSEG; seg++)
            s += g_part[(seg * BATCH + b) * (J54 * 3) + t];
        jall[t] = s;
    }
    __syncthreads();
    if (t < 3) {
        int a = is64 ? jmap[2 * 27] : jmap[27];
        int c = is64 ? jmap[2 * 28] : jmap[28];
        float p = 0.5f * (jall[a * 3 + t] + jall[c * 3 + t]);
        pel[t] = p;
        g_pel[b * 3 + t] = p;
        out[(size_t)BATCH * N3 + (size_t)BATCH * 147 + b * 3 + t] = p;
    }
    __syncthreads();
    if (t < 147) {
        int i = t / 3, d = t % 3;
        int j = is64 ? jmap[2 * i] : jmap[i];
        out[(size_t)BATCH * N3 + b * 147 + t] = jall[j * 3 + d] - pel[d];
    }
}

// ============================================================================
// K7: v -= pelvis
// ============================================================================
__global__ void subv_kernel(float* __restrict__ out) {
    int idx = blockIdx.x * 256 + threadIdx.x;
    if (idx < BATCH * N3) {
        int b = idx / N3;
        int d = idx % 3;
        out[idx] -= g_pel[b * 3 + d];
    }
}

// ============================================================================
extern "C" void kernel_launch(void* const* d_in, const int* in_sizes, int n_in,
                              void* d_out, int out_size) {
    const float* pose      = (const float*)d_in[0];
    const float* beta      = (const float*)d_in[1];
    const float* vtemp     = (const float*)d_in[2];
    const float* shapedirs = (const float*)d_in[3];
    const float* posedirs  = (const float*)d_in[4];
    const float* weights   = (const float*)d_in[5];
    const float* Jreg      = (const float*)d_in[6];
    const float* Jspin     = (const float*)d_in[7];
    const float* Jextra    = (const float*)d_in[8];
    const int* jmap        = (const int*)d_in[10];
    float* out = (float*)d_out;

    sniff_kernel<<<1, 32>>>(jmap);
    jm_kernel<<<72, 256>>>(Jreg, shapedirs, vtemp);
    pose_kernel<<<BATCH, 32>>>(pose, beta);
    at_kernel<<<(KDIM * BATCH) / 256, 256>>>();
    pack_kernel<<<NP / 32, 256>>>(posedirs, shapedirs);
    gemm_tf32_kernel<<<dim3(NP / 128, BATCH / 128), 256>>>(vtemp);
    skin_kernel<<<dim3((NV + 127) / 128, BATCH / 8), 128>>>(weights, out);
    joints_kernel<<<dim3(BATCH / 16, NSEG), 256>>>(Jreg, Jspin, Jextra, out);
    finalize_kernel<<<BATCH, 192>>>(jmap, out);
    subv_kernel<<<(BATCH * N3 + 255) / 256, 256>>>(out);
}